// round 16
// baseline (speedup 1.0000x reference)
#include <cuda_runtime.h>
#include <cuda_bf16.h>
#include <cstdint>

// ---------------------------------------------------------------------------
// Problem constants
// ---------------------------------------------------------------------------
#define N_SRC0 700000
#define N_DST0 51200
#define N_DST1 5120
#define N_DST2 1024
#define N_EDGE0 768000
#define N_EDGE1 51200
#define N_EDGE2 5120
#define IN_FEATS 128
#define N_HIDDEN 256
#define N_CLASSES 47

// ---------------------------------------------------------------------------
// Scratch (__device__ globals; 16B aligned for float4 / red.v4)
// ---------------------------------------------------------------------------
__device__ __align__(16) float g_msg0[(size_t)N_DST0 * IN_FEATS];
__device__ __align__(16) float g_deg0[N_DST0];
__device__ __align__(16) float g_h1[(size_t)N_DST0 * N_HIDDEN];
__device__ __align__(16) float g_msg1[(size_t)N_DST1 * N_HIDDEN];
__device__ __align__(16) float g_deg1[N_DST1];
__device__ __align__(16) float g_h2[(size_t)N_DST1 * N_HIDDEN];
__device__ __align__(16) float g_msg2[(size_t)N_DST2 * N_HIDDEN];
__device__ __align__(16) float g_deg2[N_DST2];

// ---------------------------------------------------------------------------
// Helpers
// ---------------------------------------------------------------------------
__device__ __forceinline__ void red_add_v4(float* addr, float4 v) {
    asm volatile("red.global.add.v4.f32 [%0], {%1, %2, %3, %4};"
                 :: "l"(addr), "f"(v.x), "f"(v.y), "f"(v.z), "f"(v.w)
                 : "memory");
}

__device__ __forceinline__ void red_add_f32(float* addr, float v) {
    asm volatile("red.global.add.f32 [%0], %1;" :: "l"(addr), "f"(v) : "memory");
}

__device__ __forceinline__ uint32_t f2tf32(float f) {
    uint32_t u;
    asm("cvt.rna.tf32.f32 %0, %1;" : "=r"(u) : "f"(f));
    return u;
}

__device__ __forceinline__ void mma_tf32(float& c0, float& c1, float& c2, float& c3,
                                         uint32_t a0, uint32_t a1, uint32_t a2, uint32_t a3,
                                         uint32_t b0, uint32_t b1) {
    asm volatile("mma.sync.aligned.m16n8k8.row.col.f32.tf32.tf32.f32 "
                 "{%0,%1,%2,%3}, {%4,%5,%6,%7}, {%8,%9}, {%0,%1,%2,%3};"
                 : "+f"(c0), "+f"(c1), "+f"(c2), "+f"(c3)
                 : "r"(a0), "r"(a1), "r"(a2), "r"(a3), "r"(b0), "r"(b1));
}

__device__ __forceinline__ float inv_deg(float d) {
    return __fdividef(1.0f, fmaxf(d, 1.0f));
}

// ---------------------------------------------------------------------------
// One fused init kernel: zero all msg/deg buffers; out = bias2 broadcast.
// ---------------------------------------------------------------------------
#define F4_MSG0 (N_DST0 * IN_FEATS / 4)
#define F4_DEG0 (N_DST0 / 4)
#define F4_MSG1 (N_DST1 * N_HIDDEN / 4)
#define F4_DEG1 (N_DST1 / 4)
#define F4_MSG2 (N_DST2 * N_HIDDEN / 4)
#define F4_DEG2 (N_DST2 / 4)
#define F4_TOTAL (F4_MSG0 + F4_DEG0 + F4_MSG1 + F4_DEG1 + F4_MSG2 + F4_DEG2)
#define OUT_ELEMS (N_DST2 * N_CLASSES)

__global__ void init_kernel(float4* __restrict__ msg0, float4* __restrict__ deg0,
                            float4* __restrict__ msg1, float4* __restrict__ deg1,
                            float4* __restrict__ msg2, float4* __restrict__ deg2,
                            float* __restrict__ out, const float* __restrict__ bias2) {
    int i = blockIdx.x * blockDim.x + threadIdx.x;
    float4 z = make_float4(0.f, 0.f, 0.f, 0.f);
    if (i < F4_TOTAL) {
        int j = i;
        if (j < F4_MSG0) { msg0[j] = z; return; }
        j -= F4_MSG0;
        if (j < F4_DEG0) { deg0[j] = z; return; }
        j -= F4_DEG0;
        if (j < F4_MSG1) { msg1[j] = z; return; }
        j -= F4_MSG1;
        if (j < F4_DEG1) { deg1[j] = z; return; }
        j -= F4_DEG1;
        if (j < F4_MSG2) { msg2[j] = z; return; }
        j -= F4_MSG2;
        deg2[j] = z;
        return;
    }
    int j = i - F4_TOTAL;
    if (j < OUT_ELEMS) out[j] = bias2[j % N_CLASSES];
}

// ---------------------------------------------------------------------------
// Edge aggregation, ILP=4 — at its composite hardware wall (closed).
// ---------------------------------------------------------------------------
template <int F>
__global__ __launch_bounds__(256)
void aggregate_kernel(const float* __restrict__ h,
                      const int* __restrict__ src,
                      const int* __restrict__ dst,
                      float* __restrict__ msg,
                      float* __restrict__ deg,
                      int n_edge) {
    constexpr int LPE = F / 16;                 // lanes per edge (8 or 16)
    int gtid = blockIdx.x * blockDim.x + threadIdx.x;
    int e    = gtid / LPE;
    int lane = gtid % LPE;
    if (e >= n_edge) return;

    int s = src[e];
    int d = dst[e];

    const float4* row = reinterpret_cast<const float4*>(h + (size_t)s * F);
    float4 v0 = __ldg(row + lane);
    float4 v1 = __ldg(row + lane + LPE);
    float4 v2 = __ldg(row + lane + 2 * LPE);
    float4 v3 = __ldg(row + lane + 3 * LPE);

    float* mrow = msg + (size_t)d * F;
    red_add_v4(mrow + (size_t)lane * 4, v0);
    red_add_v4(mrow + (size_t)(lane + LPE) * 4, v1);
    red_add_v4(mrow + (size_t)(lane + 2 * LPE) * 4, v2);
    red_add_v4(mrow + (size_t)(lane + 3 * LPE) * 4, v3);

    if (lane == 0) red_add_f32(&deg[d], 1.0f);
}

// ---------------------------------------------------------------------------
// tf32 tensor-core dual GEMM (layers 0 and 1), OCCUPANCY STEP 2:
// BM=64, BN=64, BK=32, 256 threads = 8 warps (4 along M x 2 along N),
// warp tile 16x32 -> acc 16 regs/thread -> 4 CTAs/SM (occ 50% vs 37.5%).
//   C = A1 @ B1 + diag(1/max(deg,1)) * A2 @ B2 + bias   (+ optional ReLU)
// Requires: N % 64 == 0, M % 64 == 0, K % 32 == 0.
// ---------------------------------------------------------------------------
template <bool RELU>
__global__ __launch_bounds__(256, 4)
void gemm2_tc_kernel(const float* __restrict__ A1, const float* __restrict__ A2,
                     const float* __restrict__ deg,
                     const float* __restrict__ B1, const float* __restrict__ B2,
                     const float* __restrict__ bias, float* __restrict__ C,
                     int M, int N, int K) {
    constexpr int BM = 64, BN = 64, BK = 32;

    __shared__ uint32_t As[BM][BK + 4];    // 9.2 KB
    __shared__ uint32_t Bs[BK][BN + 8];    // 9.2 KB

    const int tid   = threadIdx.x;
    const int warp  = tid >> 5;
    const int lane  = tid & 31;
    const int g     = lane >> 2;
    const int t     = lane & 3;
    const int warpM = (warp & 3) * 16;     // 4 warps along M
    const int warpN = (warp >> 2) * 32;    // 2 warps along N
    const int rowBase = blockIdx.y * BM;
    const int colBase = blockIdx.x * BN;

    float acc[4][4];                       // 4 n-tiles of m16n8
#pragma unroll
    for (int j = 0; j < 4; ++j)
#pragma unroll
        for (int r = 0; r < 4; ++r) acc[j][r] = 0.f;

#pragma unroll
    for (int phase = 0; phase < 2; ++phase) {
        const float* __restrict__ A = phase ? A2 : A1;
        const float* __restrict__ B = phase ? B2 : B1;

        for (int k0 = 0; k0 < K; k0 += BK) {
            // --- A tile: 64x32 floats = 512 float4, 2 per thread ---
#pragma unroll
            for (int i = 0; i < 2; ++i) {
                int idx = i * 256 + tid;
                int row = idx >> 3;        // 0..63
                int c4  = idx & 7;         // 0..7
                float4 v = *reinterpret_cast<const float4*>(
                    A + (size_t)(rowBase + row) * K + k0 + c4 * 4);
                if (phase == 1) {
                    float s = inv_deg(deg[rowBase + row]);
                    v.x *= s; v.y *= s; v.z *= s; v.w *= s;
                }
                uint4 u = make_uint4(f2tf32(v.x), f2tf32(v.y), f2tf32(v.z), f2tf32(v.w));
                *reinterpret_cast<uint4*>(&As[row][c4 * 4]) = u;
            }
            // --- B tile: 32x64 floats = 512 float4, 2 per thread ---
#pragma unroll
            for (int i = 0; i < 2; ++i) {
                int idx = i * 256 + tid;
                int row = idx >> 4;        // 0..31
                int c4  = idx & 15;        // 0..15
                float4 v = *reinterpret_cast<const float4*>(
                    B + (size_t)(k0 + row) * N + colBase + c4 * 4);
                uint4 u = make_uint4(f2tf32(v.x), f2tf32(v.y), f2tf32(v.z), f2tf32(v.w));
                *reinterpret_cast<uint4*>(&Bs[row][c4 * 4]) = u;
            }
            __syncthreads();

#pragma unroll
            for (int ks = 0; ks < BK / 8; ++ks) {
                const int kb = ks * 8;
                // A fragment (one m16 tile; bank = (4g + t + ...) spans 32)
                uint32_t a0 = As[warpM + g][kb + t];
                uint32_t a1 = As[warpM + 8 + g][kb + t];
                uint32_t a2 = As[warpM + g][kb + 4 + t];
                uint32_t a3 = As[warpM + 8 + g][kb + 4 + t];
                // B fragments (4 n-tiles; bank = (8t + g + ...) spans 32)
                uint32_t bf[4][2];
#pragma unroll
                for (int nt = 0; nt < 4; ++nt) {
                    int n = warpN + nt * 8;
                    bf[nt][0] = Bs[kb + t][n + g];
                    bf[nt][1] = Bs[kb + 4 + t][n + g];
                }
#pragma unroll
                for (int nt = 0; nt < 4; ++nt)
                    mma_tf32(acc[nt][0], acc[nt][1], acc[nt][2], acc[nt][3],
                             a0, a1, a2, a3, bf[nt][0], bf[nt][1]);
            }
            __syncthreads();
        }
    }

    // --- epilogue: bias (+ReLU), float2 stores ---
#pragma unroll
    for (int nt = 0; nt < 4; ++nt) {
        int c  = colBase + warpN + nt * 8 + 2 * t;
        float bx = bias[c], by = bias[c + 1];
        int r0 = rowBase + warpM + g;
        float v0 = acc[nt][0] + bx;
        float v1 = acc[nt][1] + by;
        float v2 = acc[nt][2] + bx;
        float v3 = acc[nt][3] + by;
        if (RELU) {
            v0 = fmaxf(v0, 0.f); v1 = fmaxf(v1, 0.f);
            v2 = fmaxf(v2, 0.f); v3 = fmaxf(v3, 0.f);
        }
        *reinterpret_cast<float2*>(C + (size_t)r0 * N + c)       = make_float2(v0, v1);
        *reinterpret_cast<float2*>(C + (size_t)(r0 + 8) * N + c) = make_float2(v2, v3);
    }
}

// ---------------------------------------------------------------------------
// Layer-2 split-K tf32 GEMM: C += A1@B1 + diag(1/deg)*A2@B2 (C holds bias).
// N = 47 (padded to 64 in smem). grid = (M/64, 4).
// ---------------------------------------------------------------------------
__global__ __launch_bounds__(128)
void gemm2_tc_splitk(const float* __restrict__ A1, const float* __restrict__ A2,
                     const float* __restrict__ deg,
                     const float* __restrict__ B1, const float* __restrict__ B2,
                     float* __restrict__ C, int M, int N, int K) {
    constexpr int BM = 64, BN = 64, BK = 32;

    __shared__ uint32_t As[BM][BK + 4];
    __shared__ uint32_t Bs[BK][BN + 8];

    const int tid   = threadIdx.x;
    const int warp  = tid >> 5;
    const int lane  = tid & 31;
    const int g     = lane >> 2;
    const int t     = lane & 3;
    const int warpM = warp * 16;
    const int rowBase = blockIdx.x * BM;

    const int phase  = blockIdx.y >> 1;
    const int kBegin = (blockIdx.y & 1) * (K / 2);
    const float* __restrict__ A = phase ? A2 : A1;
    const float* __restrict__ B = phase ? B2 : B1;

    float acc[8][4];
#pragma unroll
    for (int i = 0; i < 8; ++i)
#pragma unroll
        for (int r = 0; r < 4; ++r) acc[i][r] = 0.f;

    for (int k0 = kBegin; k0 < kBegin + K / 2; k0 += BK) {
#pragma unroll
        for (int i = 0; i < 4; ++i) {
            int idx = i * 128 + tid;
            int row = idx >> 3;
            int c4  = idx & 7;
            float4 v = *reinterpret_cast<const float4*>(
                A + (size_t)(rowBase + row) * K + k0 + c4 * 4);
            if (phase == 1) {
                float s = inv_deg(deg[rowBase + row]);
                v.x *= s; v.y *= s; v.z *= s; v.w *= s;
            }
            uint4 u = make_uint4(f2tf32(v.x), f2tf32(v.y), f2tf32(v.z), f2tf32(v.w));
            *reinterpret_cast<uint4*>(&As[row][c4 * 4]) = u;
        }
#pragma unroll
        for (int i = 0; i < 16; ++i) {
            int idx = i * 128 + tid;
            int row = idx >> 6;
            int col = idx & 63;
            float v = (col < N) ? B[(size_t)(k0 + row) * N + col] : 0.f;
            Bs[row][col] = f2tf32(v);
        }
        __syncthreads();

#pragma unroll
        for (int ks = 0; ks < BK / 8; ++ks) {
            const int kb = ks * 8;
            uint32_t a0 = As[warpM + g][kb + t];
            uint32_t a1 = As[warpM + 8 + g][kb + t];
            uint32_t a2 = As[warpM + g][kb + 4 + t];
            uint32_t a3 = As[warpM + 8 + g][kb + 4 + t];
#pragma unroll
            for (int nt = 0; nt < 8; ++nt) {
                uint32_t b0 = Bs[kb + t][nt * 8 + g];
                uint32_t b1 = Bs[kb + 4 + t][nt * 8 + g];
                mma_tf32(acc[nt][0], acc[nt][1], acc[nt][2], acc[nt][3],
                         a0, a1, a2, a3, b0, b1);
            }
        }
        __syncthreads();
    }

    int r0 = rowBase + warpM + g;
#pragma unroll
    for (int nt = 0; nt < 8; ++nt) {
        int c = nt * 8 + 2 * t;
        if (c < N) {
            red_add_f32(C + (size_t)r0 * N + c, acc[nt][0]);
            red_add_f32(C + (size_t)(r0 + 8) * N + c, acc[nt][2]);
        }
        if (c + 1 < N) {
            red_add_f32(C + (size_t)r0 * N + c + 1, acc[nt][1]);
            red_add_f32(C + (size_t)(r0 + 8) * N + c + 1, acc[nt][3]);
        }
    }
}

// ---------------------------------------------------------------------------
// Launch (serial pipeline)
// ---------------------------------------------------------------------------
static inline int cdiv(int a, int b) { return (a + b - 1) / b; }

extern "C" void kernel_launch(void* const* d_in, const int* in_sizes, int n_in,
                              void* d_out, int out_size) {
    const float* x    = (const float*)d_in[0];
    const int*   src0 = (const int*)d_in[1];
    const int*   dst0 = (const int*)d_in[2];
    const int*   src1 = (const int*)d_in[3];
    const int*   dst1 = (const int*)d_in[4];
    const int*   src2 = (const int*)d_in[5];
    const int*   dst2 = (const int*)d_in[6];
    const float* Ws0  = (const float*)d_in[7];
    const float* Wn0  = (const float*)d_in[8];
    const float* b0   = (const float*)d_in[9];
    const float* Ws1  = (const float*)d_in[10];
    const float* Wn1  = (const float*)d_in[11];
    const float* b1   = (const float*)d_in[12];
    const float* Ws2  = (const float*)d_in[13];
    const float* Wn2  = (const float*)d_in[14];
    const float* b2   = (const float*)d_in[15];
    float* out = (float*)d_out;

    float *msg0, *deg0, *h1, *msg1, *deg1, *h2, *msg2, *deg2;
    cudaGetSymbolAddress((void**)&msg0, g_msg0);
    cudaGetSymbolAddress((void**)&deg0, g_deg0);
    cudaGetSymbolAddress((void**)&h1,   g_h1);
    cudaGetSymbolAddress((void**)&msg1, g_msg1);
    cudaGetSymbolAddress((void**)&deg1, g_deg1);
    cudaGetSymbolAddress((void**)&h2,   g_h2);
    cudaGetSymbolAddress((void**)&msg2, g_msg2);
    cudaGetSymbolAddress((void**)&deg2, g_deg2);

    const int TPB = 256;

    // ---- one fused init: zero all msg/deg, out = bias2 ----
    init_kernel<<<cdiv(F4_TOTAL + OUT_ELEMS, TPB), TPB>>>(
        (float4*)msg0, (float4*)deg0, (float4*)msg1, (float4*)deg1,
        (float4*)msg2, (float4*)deg2, out, b2);

    // ======================= Layer 0 =======================
    {
        long long threads = (long long)N_EDGE0 * (IN_FEATS / 16);
        aggregate_kernel<IN_FEATS><<<(int)((threads + TPB - 1) / TPB), TPB>>>(
            x, src0, dst0, msg0, deg0, N_EDGE0);

        dim3 grid(N_HIDDEN / 64, N_DST0 / 64);
        gemm2_tc_kernel<true><<<grid, 256>>>(x, msg0, deg0, Ws0, Wn0, b0, h1,
                                             N_DST0, N_HIDDEN, IN_FEATS);
    }

    // ======================= Layer 1 =======================
    {
        long long threads = (long long)N_EDGE1 * (N_HIDDEN / 16);
        aggregate_kernel<N_HIDDEN><<<(int)((threads + TPB - 1) / TPB), TPB>>>(
            h1, src1, dst1, msg1, deg1, N_EDGE1);

        dim3 grid(N_HIDDEN / 64, N_DST1 / 64);
        gemm2_tc_kernel<true><<<grid, 256>>>(h1, msg1, deg1, Ws1, Wn1, b1, h2,
                                             N_DST1, N_HIDDEN, N_HIDDEN);
    }

    // ======================= Layer 2 =======================
    {
        long long threads = (long long)N_EDGE2 * (N_HIDDEN / 16);
        aggregate_kernel<N_HIDDEN><<<(int)((threads + TPB - 1) / TPB), TPB>>>(
            h2, src2, dst2, msg2, deg2, N_EDGE2);

        dim3 grid2(N_DST2 / 64, 4);
        gemm2_tc_splitk<<<grid2, 128>>>(h2, msg2, deg2, Ws2, Wn2, out,
                                        N_DST2, N_CLASSES, N_HIDDEN);
    }

    (void)in_sizes; (void)n_in; (void)out_size;
}

// round 17
// speedup vs baseline: 1.0397x; 1.0397x over previous
#include <cuda_runtime.h>
#include <cuda_bf16.h>
#include <cstdint>

// ---------------------------------------------------------------------------
// Problem constants
// ---------------------------------------------------------------------------
#define N_SRC0 700000
#define N_DST0 51200
#define N_DST1 5120
#define N_DST2 1024
#define N_EDGE0 768000
#define N_EDGE1 51200
#define N_EDGE2 5120
#define IN_FEATS 128
#define N_HIDDEN 256
#define N_CLASSES 47

// ---------------------------------------------------------------------------
// Scratch (__device__ globals; 16B aligned for float4 / red.v4)
// ---------------------------------------------------------------------------
__device__ __align__(16) float g_msg0[(size_t)N_DST0 * IN_FEATS];
__device__ __align__(16) float g_deg0[N_DST0];
__device__ __align__(16) float g_h1[(size_t)N_DST0 * N_HIDDEN];
__device__ __align__(16) float g_msg1[(size_t)N_DST1 * N_HIDDEN];
__device__ __align__(16) float g_deg1[N_DST1];
__device__ __align__(16) float g_h2[(size_t)N_DST1 * N_HIDDEN];
__device__ __align__(16) float g_msg2[(size_t)N_DST2 * N_HIDDEN];
__device__ __align__(16) float g_deg2[N_DST2];

// ---------------------------------------------------------------------------
// Helpers
// ---------------------------------------------------------------------------
__device__ __forceinline__ void red_add_v4(float* addr, float4 v) {
    asm volatile("red.global.add.v4.f32 [%0], {%1, %2, %3, %4};"
                 :: "l"(addr), "f"(v.x), "f"(v.y), "f"(v.z), "f"(v.w)
                 : "memory");
}

__device__ __forceinline__ void red_add_f32(float* addr, float v) {
    asm volatile("red.global.add.f32 [%0], %1;" :: "l"(addr), "f"(v) : "memory");
}

__device__ __forceinline__ uint32_t f2tf32(float f) {
    uint32_t u;
    asm("cvt.rna.tf32.f32 %0, %1;" : "=r"(u) : "f"(f));
    return u;
}

__device__ __forceinline__ void mma_tf32(float& c0, float& c1, float& c2, float& c3,
                                         uint32_t a0, uint32_t a1, uint32_t a2, uint32_t a3,
                                         uint32_t b0, uint32_t b1) {
    asm volatile("mma.sync.aligned.m16n8k8.row.col.f32.tf32.tf32.f32 "
                 "{%0,%1,%2,%3}, {%4,%5,%6,%7}, {%8,%9}, {%0,%1,%2,%3};"
                 : "+f"(c0), "+f"(c1), "+f"(c2), "+f"(c3)
                 : "r"(a0), "r"(a1), "r"(a2), "r"(a3), "r"(b0), "r"(b1));
}

__device__ __forceinline__ float inv_deg(float d) {
    return __fdividef(1.0f, fmaxf(d, 1.0f));
}

// ---------------------------------------------------------------------------
// Split init:
//  initA: msg0 + deg0 (the only agg0 dependencies)
//  initB: msg1/deg1/msg2/deg2 + out=bias2 (runs on a side stream under agg0)
// ---------------------------------------------------------------------------
#define F4_MSG0 (N_DST0 * IN_FEATS / 4)
#define F4_DEG0 (N_DST0 / 4)
#define F4_A_TOTAL (F4_MSG0 + F4_DEG0)

#define F4_MSG1 (N_DST1 * N_HIDDEN / 4)
#define F4_DEG1 (N_DST1 / 4)
#define F4_MSG2 (N_DST2 * N_HIDDEN / 4)
#define F4_DEG2 (N_DST2 / 4)
#define F4_B_TOTAL (F4_MSG1 + F4_DEG1 + F4_MSG2 + F4_DEG2)
#define OUT_ELEMS (N_DST2 * N_CLASSES)

__global__ void initA_kernel(float4* __restrict__ msg0, float4* __restrict__ deg0) {
    int i = blockIdx.x * blockDim.x + threadIdx.x;
    float4 z = make_float4(0.f, 0.f, 0.f, 0.f);
    if (i < F4_MSG0) { msg0[i] = z; return; }
    i -= F4_MSG0;
    if (i < F4_DEG0) deg0[i] = z;
}

__global__ void initB_kernel(float4* __restrict__ msg1, float4* __restrict__ deg1,
                             float4* __restrict__ msg2, float4* __restrict__ deg2,
                             float* __restrict__ out, const float* __restrict__ bias2) {
    int i = blockIdx.x * blockDim.x + threadIdx.x;
    float4 z = make_float4(0.f, 0.f, 0.f, 0.f);
    if (i < F4_B_TOTAL) {
        int j = i;
        if (j < F4_MSG1) { msg1[j] = z; return; }
        j -= F4_MSG1;
        if (j < F4_DEG1) { deg1[j] = z; return; }
        j -= F4_DEG1;
        if (j < F4_MSG2) { msg2[j] = z; return; }
        j -= F4_MSG2;
        deg2[j] = z;
        return;
    }
    int j = i - F4_B_TOTAL;
    if (j < OUT_ELEMS) out[j] = bias2[j % N_CLASSES];
}

// ---------------------------------------------------------------------------
// Edge aggregation, ILP=4 — at its composite hardware wall (closed).
// ---------------------------------------------------------------------------
template <int F>
__global__ __launch_bounds__(256)
void aggregate_kernel(const float* __restrict__ h,
                      const int* __restrict__ src,
                      const int* __restrict__ dst,
                      float* __restrict__ msg,
                      float* __restrict__ deg,
                      int n_edge) {
    constexpr int LPE = F / 16;                 // lanes per edge (8 or 16)
    int gtid = blockIdx.x * blockDim.x + threadIdx.x;
    int e    = gtid / LPE;
    int lane = gtid % LPE;
    if (e >= n_edge) return;

    int s = src[e];
    int d = dst[e];

    const float4* row = reinterpret_cast<const float4*>(h + (size_t)s * F);
    float4 v0 = __ldg(row + lane);
    float4 v1 = __ldg(row + lane + LPE);
    float4 v2 = __ldg(row + lane + 2 * LPE);
    float4 v3 = __ldg(row + lane + 3 * LPE);

    float* mrow = msg + (size_t)d * F;
    red_add_v4(mrow + (size_t)lane * 4, v0);
    red_add_v4(mrow + (size_t)(lane + LPE) * 4, v1);
    red_add_v4(mrow + (size_t)(lane + 2 * LPE) * 4, v2);
    red_add_v4(mrow + (size_t)(lane + 3 * LPE) * 4, v3);

    if (lane == 0) red_add_f32(&deg[d], 1.0f);
}

// ---------------------------------------------------------------------------
// tf32 tensor-core dual GEMM — exact R15 winner (BM=64, BN=128, BK=32,
// 8 warps = 4Mx2N, warp tile 16x64, 3 CTAs/SM; bracketed optimum).
//   C = A1 @ B1 + diag(1/max(deg,1)) * A2 @ B2 + bias   (+ optional ReLU)
// Requires: N % 128 == 0, M % 64 == 0, K % 32 == 0.
// ---------------------------------------------------------------------------
template <bool RELU>
__global__ __launch_bounds__(256, 3)
void gemm2_tc_kernel(const float* __restrict__ A1, const float* __restrict__ A2,
                     const float* __restrict__ deg,
                     const float* __restrict__ B1, const float* __restrict__ B2,
                     const float* __restrict__ bias, float* __restrict__ C,
                     int M, int N, int K) {
    constexpr int BM = 64, BN = 128, BK = 32;

    __shared__ uint32_t As[BM][BK + 4];    // 9.2 KB
    __shared__ uint32_t Bs[BK][BN + 8];    // 17.4 KB

    const int tid   = threadIdx.x;
    const int warp  = tid >> 5;
    const int lane  = tid & 31;
    const int g     = lane >> 2;
    const int t     = lane & 3;
    const int warpM = (warp & 3) * 16;     // 4 warps along M
    const int warpN = (warp >> 2) * 64;    // 2 warps along N
    const int rowBase = blockIdx.y * BM;
    const int colBase = blockIdx.x * BN;

    float acc[8][4];                       // 8 n-tiles of m16n8
#pragma unroll
    for (int j = 0; j < 8; ++j)
#pragma unroll
        for (int r = 0; r < 4; ++r) acc[j][r] = 0.f;

#pragma unroll
    for (int phase = 0; phase < 2; ++phase) {
        const float* __restrict__ A = phase ? A2 : A1;
        const float* __restrict__ B = phase ? B2 : B1;

        for (int k0 = 0; k0 < K; k0 += BK) {
            // --- A tile: 64x32 floats = 512 float4, 2 per thread ---
#pragma unroll
            for (int i = 0; i < 2; ++i) {
                int idx = i * 256 + tid;
                int row = idx >> 3;        // 0..63
                int c4  = idx & 7;         // 0..7
                float4 v = *reinterpret_cast<const float4*>(
                    A + (size_t)(rowBase + row) * K + k0 + c4 * 4);
                if (phase == 1) {
                    float s = inv_deg(deg[rowBase + row]);
                    v.x *= s; v.y *= s; v.z *= s; v.w *= s;
                }
                uint4 u = make_uint4(f2tf32(v.x), f2tf32(v.y), f2tf32(v.z), f2tf32(v.w));
                *reinterpret_cast<uint4*>(&As[row][c4 * 4]) = u;
            }
            // --- B tile: 32x128 floats = 1024 float4, 4 per thread ---
#pragma unroll
            for (int i = 0; i < 4; ++i) {
                int idx = i * 256 + tid;
                int row = idx >> 5;        // 0..31
                int c4  = idx & 31;        // 0..31
                float4 v = *reinterpret_cast<const float4*>(
                    B + (size_t)(k0 + row) * N + colBase + c4 * 4);
                uint4 u = make_uint4(f2tf32(v.x), f2tf32(v.y), f2tf32(v.z), f2tf32(v.w));
                *reinterpret_cast<uint4*>(&Bs[row][c4 * 4]) = u;
            }
            __syncthreads();

#pragma unroll
            for (int ks = 0; ks < BK / 8; ++ks) {
                const int kb = ks * 8;
                uint32_t a0 = As[warpM + g][kb + t];
                uint32_t a1 = As[warpM + 8 + g][kb + t];
                uint32_t a2 = As[warpM + g][kb + 4 + t];
                uint32_t a3 = As[warpM + 8 + g][kb + 4 + t];
                uint32_t bf[8][2];
#pragma unroll
                for (int nt = 0; nt < 8; ++nt) {
                    int n = warpN + nt * 8;
                    bf[nt][0] = Bs[kb + t][n + g];
                    bf[nt][1] = Bs[kb + 4 + t][n + g];
                }
#pragma unroll
                for (int nt = 0; nt < 8; ++nt)
                    mma_tf32(acc[nt][0], acc[nt][1], acc[nt][2], acc[nt][3],
                             a0, a1, a2, a3, bf[nt][0], bf[nt][1]);
            }
            __syncthreads();
        }
    }

    // --- epilogue: bias (+ReLU), float2 stores ---
#pragma unroll
    for (int nt = 0; nt < 8; ++nt) {
        int c  = colBase + warpN + nt * 8 + 2 * t;
        float bx = bias[c], by = bias[c + 1];
        int r0 = rowBase + warpM + g;
        float v0 = acc[nt][0] + bx;
        float v1 = acc[nt][1] + by;
        float v2 = acc[nt][2] + bx;
        float v3 = acc[nt][3] + by;
        if (RELU) {
            v0 = fmaxf(v0, 0.f); v1 = fmaxf(v1, 0.f);
            v2 = fmaxf(v2, 0.f); v3 = fmaxf(v3, 0.f);
        }
        *reinterpret_cast<float2*>(C + (size_t)r0 * N + c)       = make_float2(v0, v1);
        *reinterpret_cast<float2*>(C + (size_t)(r0 + 8) * N + c) = make_float2(v2, v3);
    }
}

// ---------------------------------------------------------------------------
// Layer-2 split-K tf32 GEMM: C += A1@B1 + diag(1/deg)*A2@B2 (C holds bias).
// N = 47 (padded to 64 in smem). grid = (M/64, 4).
// ---------------------------------------------------------------------------
__global__ __launch_bounds__(128)
void gemm2_tc_splitk(const float* __restrict__ A1, const float* __restrict__ A2,
                     const float* __restrict__ deg,
                     const float* __restrict__ B1, const float* __restrict__ B2,
                     float* __restrict__ C, int M, int N, int K) {
    constexpr int BM = 64, BN = 64, BK = 32;

    __shared__ uint32_t As[BM][BK + 4];
    __shared__ uint32_t Bs[BK][BN + 8];

    const int tid   = threadIdx.x;
    const int warp  = tid >> 5;
    const int lane  = tid & 31;
    const int g     = lane >> 2;
    const int t     = lane & 3;
    const int warpM = warp * 16;
    const int rowBase = blockIdx.x * BM;

    const int phase  = blockIdx.y >> 1;
    const int kBegin = (blockIdx.y & 1) * (K / 2);
    const float* __restrict__ A = phase ? A2 : A1;
    const float* __restrict__ B = phase ? B2 : B1;

    float acc[8][4];
#pragma unroll
    for (int i = 0; i < 8; ++i)
#pragma unroll
        for (int r = 0; r < 4; ++r) acc[i][r] = 0.f;

    for (int k0 = kBegin; k0 < kBegin + K / 2; k0 += BK) {
#pragma unroll
        for (int i = 0; i < 4; ++i) {
            int idx = i * 128 + tid;
            int row = idx >> 3;
            int c4  = idx & 7;
            float4 v = *reinterpret_cast<const float4*>(
                A + (size_t)(rowBase + row) * K + k0 + c4 * 4);
            if (phase == 1) {
                float s = inv_deg(deg[rowBase + row]);
                v.x *= s; v.y *= s; v.z *= s; v.w *= s;
            }
            uint4 u = make_uint4(f2tf32(v.x), f2tf32(v.y), f2tf32(v.z), f2tf32(v.w));
            *reinterpret_cast<uint4*>(&As[row][c4 * 4]) = u;
        }
#pragma unroll
        for (int i = 0; i < 16; ++i) {
            int idx = i * 128 + tid;
            int row = idx >> 6;
            int col = idx & 63;
            float v = (col < N) ? B[(size_t)(k0 + row) * N + col] : 0.f;
            Bs[row][col] = f2tf32(v);
        }
        __syncthreads();

#pragma unroll
        for (int ks = 0; ks < BK / 8; ++ks) {
            const int kb = ks * 8;
            uint32_t a0 = As[warpM + g][kb + t];
            uint32_t a1 = As[warpM + 8 + g][kb + t];
            uint32_t a2 = As[warpM + g][kb + 4 + t];
            uint32_t a3 = As[warpM + 8 + g][kb + 4 + t];
#pragma unroll
            for (int nt = 0; nt < 8; ++nt) {
                uint32_t b0 = Bs[kb + t][nt * 8 + g];
                uint32_t b1 = Bs[kb + 4 + t][nt * 8 + g];
                mma_tf32(acc[nt][0], acc[nt][1], acc[nt][2], acc[nt][3],
                         a0, a1, a2, a3, b0, b1);
            }
        }
        __syncthreads();
    }

    int r0 = rowBase + warpM + g;
#pragma unroll
    for (int nt = 0; nt < 8; ++nt) {
        int c = nt * 8 + 2 * t;
        if (c < N) {
            red_add_f32(C + (size_t)r0 * N + c, acc[nt][0]);
            red_add_f32(C + (size_t)(r0 + 8) * N + c, acc[nt][2]);
        }
        if (c + 1 < N) {
            red_add_f32(C + (size_t)r0 * N + c + 1, acc[nt][1]);
            red_add_f32(C + (size_t)(r0 + 8) * N + c + 1, acc[nt][3]);
        }
    }
}

// ---------------------------------------------------------------------------
// Launch: serial pipeline; initB (non-layer-0 zeroing + out bias) runs on a
// side stream underneath agg0. Stream/events lazily created, never destroyed.
// ---------------------------------------------------------------------------
static inline int cdiv(int a, int b) { return (a + b - 1) / b; }

extern "C" void kernel_launch(void* const* d_in, const int* in_sizes, int n_in,
                              void* d_out, int out_size) {
    const float* x    = (const float*)d_in[0];
    const int*   src0 = (const int*)d_in[1];
    const int*   dst0 = (const int*)d_in[2];
    const int*   src1 = (const int*)d_in[3];
    const int*   dst1 = (const int*)d_in[4];
    const int*   src2 = (const int*)d_in[5];
    const int*   dst2 = (const int*)d_in[6];
    const float* Ws0  = (const float*)d_in[7];
    const float* Wn0  = (const float*)d_in[8];
    const float* b0   = (const float*)d_in[9];
    const float* Ws1  = (const float*)d_in[10];
    const float* Wn1  = (const float*)d_in[11];
    const float* b1   = (const float*)d_in[12];
    const float* Ws2  = (const float*)d_in[13];
    const float* Wn2  = (const float*)d_in[14];
    const float* b2   = (const float*)d_in[15];
    float* out = (float*)d_out;

    float *msg0, *deg0, *h1, *msg1, *deg1, *h2, *msg2, *deg2;
    cudaGetSymbolAddress((void**)&msg0, g_msg0);
    cudaGetSymbolAddress((void**)&deg0, g_deg0);
    cudaGetSymbolAddress((void**)&h1,   g_h1);
    cudaGetSymbolAddress((void**)&msg1, g_msg1);
    cudaGetSymbolAddress((void**)&deg1, g_deg1);
    cudaGetSymbolAddress((void**)&h2,   g_h2);
    cudaGetSymbolAddress((void**)&msg2, g_msg2);
    cudaGetSymbolAddress((void**)&deg2, g_deg2);

    static cudaStream_t side = nullptr;
    static cudaEvent_t evFork = nullptr, evJoin = nullptr;
    if (!side) {
        cudaStreamCreateWithFlags(&side, cudaStreamNonBlocking);
        cudaEventCreateWithFlags(&evFork, cudaEventDisableTiming);
        cudaEventCreateWithFlags(&evJoin, cudaEventDisableTiming);
    }

    const int TPB = 256;
    cudaStream_t main = 0;

    // ---- initA: msg0+deg0 (agg0 deps) on main ----
    initA_kernel<<<cdiv(F4_A_TOTAL, TPB), TPB, 0, main>>>(
        (float4*)msg0, (float4*)deg0);

    // fork: initB runs beside agg0
    cudaEventRecord(evFork, main);
    cudaStreamWaitEvent(side, evFork, 0);
    initB_kernel<<<cdiv(F4_B_TOTAL + OUT_ELEMS, TPB), TPB, 0, side>>>(
        (float4*)msg1, (float4*)deg1, (float4*)msg2, (float4*)deg2, out, b2);
    cudaEventRecord(evJoin, side);

    // ======================= Layer 0 =======================
    {
        long long threads = (long long)N_EDGE0 * (IN_FEATS / 16);
        aggregate_kernel<IN_FEATS><<<(int)((threads + TPB - 1) / TPB), TPB, 0, main>>>(
            x, src0, dst0, msg0, deg0, N_EDGE0);

        // join: everything after here may touch msg1/deg1/msg2/deg2/out
        cudaStreamWaitEvent(main, evJoin, 0);

        dim3 grid(N_HIDDEN / 128, N_DST0 / 64);
        gemm2_tc_kernel<true><<<grid, 256, 0, main>>>(x, msg0, deg0, Ws0, Wn0, b0, h1,
                                                      N_DST0, N_HIDDEN, IN_FEATS);
    }

    // ======================= Layer 1 =======================
    {
        long long threads = (long long)N_EDGE1 * (N_HIDDEN / 16);
        aggregate_kernel<N_HIDDEN><<<(int)((threads + TPB - 1) / TPB), TPB, 0, main>>>(
            h1, src1, dst1, msg1, deg1, N_EDGE1);

        dim3 grid(N_HIDDEN / 128, N_DST1 / 64);
        gemm2_tc_kernel<true><<<grid, 256, 0, main>>>(h1, msg1, deg1, Ws1, Wn1, b1, h2,
                                                      N_DST1, N_HIDDEN, N_HIDDEN);
    }

    // ======================= Layer 2 =======================
    {
        long long threads = (long long)N_EDGE2 * (N_HIDDEN / 16);
        aggregate_kernel<N_HIDDEN><<<(int)((threads + TPB - 1) / TPB), TPB, 0, main>>>(
            h2, src2, dst2, msg2, deg2, N_EDGE2);

        dim3 grid2(N_DST2 / 64, 4);
        gemm2_tc_splitk<<<grid2, 128, 0, main>>>(h2, msg2, deg2, Ws2, Wn2, out,
                                                 N_DST2, N_CLASSES, N_HIDDEN);
    }

    (void)in_sizes; (void)n_in; (void)out_size;
}